// round 2
// baseline (speedup 1.0000x reference)
#include <cuda_runtime.h>
#include <cuda_bf16.h>
#include <math.h>

#define H   1024
#define L   512
#define V   50257
#define H3  3072

// ---------------- scratch (device globals; no allocations allowed) ----------
__device__ float     g_a[L];            // raw attention scores
__device__ float     g_partial[16][H];  // partial attn_applied (per l-chunk)
__device__ float     g_applied[H];      // attn_applied
__device__ float     g_x[H];            // relu(combine)
__device__ float     g_gh[H3];          // h0 @ W_hh.T + b_hh
__device__ float     g_hnew[H];         // new hidden
__device__ unsigned  g_maxbits;         // order-encoded max logit
__device__ float     g_sumpart[64];     // partial sum-exp

// ---------------- helpers ---------------------------------------------------
__device__ __forceinline__ float dot4(float4 a, float4 b) {
    return a.x * b.x + a.y * b.y + a.z * b.z + a.w * b.w;
}
// streaming (evict-first) float4 load for read-once weight matrices
__device__ __forceinline__ float4 ld_stream(const float4* p) {
    return __ldcs(p);
}

__device__ __forceinline__ float warpReduceSum(float v) {
#pragma unroll
    for (int o = 16; o; o >>= 1) v += __shfl_xor_sync(0xffffffffu, v, o);
    return v;
}
__device__ __forceinline__ float warpReduceMax(float v) {
#pragma unroll
    for (int o = 16; o; o >>= 1) v = fmaxf(v, __shfl_xor_sync(0xffffffffu, v, o));
    return v;
}

// block reduce for blockDim.x == 256; result broadcast to all threads
__device__ float blockReduceSum(float v) {
    __shared__ float s[9];
    int lane = threadIdx.x & 31, wid = threadIdx.x >> 5;
    v = warpReduceSum(v);
    __syncthreads();
    if (lane == 0) s[wid] = v;
    __syncthreads();
    if (wid == 0) {
        float x = (lane < 8) ? s[lane] : 0.0f;
        x = warpReduceSum(x);
        if (lane == 0) s[8] = x;
    }
    __syncthreads();
    return s[8];
}
__device__ float blockReduceMax(float v) {
    __shared__ float s[9];
    int lane = threadIdx.x & 31, wid = threadIdx.x >> 5;
    v = warpReduceMax(v);
    __syncthreads();
    if (lane == 0) s[wid] = v;
    __syncthreads();
    if (wid == 0) {
        float x = (lane < 8) ? s[lane] : -3.4e38f;
        x = warpReduceMax(x);
        if (lane == 0) s[8] = x;
    }
    __syncthreads();
    return s[8];
}

__device__ __forceinline__ unsigned ordEnc(float f) {
    unsigned u = __float_as_uint(f);
    return (u & 0x80000000u) ? ~u : (u | 0x80000000u);
}
__device__ __forceinline__ float ordDec(unsigned u) {
    u = (u & 0x80000000u) ? (u & 0x7fffffffu) : ~u;
    return __uint_as_float(u);
}
__device__ __forceinline__ float sigm(float x) { return 1.0f / (1.0f + expf(-x)); }

// ---------------- K1: attention scores a = [emb,h0] @ attn_W.T + b ----------
__global__ void k_scores(const int* __restrict__ ids, const float* __restrict__ hid,
                         const float* __restrict__ emb, const float* __restrict__ attn_W,
                         const float* __restrict__ attn_b) {
    int row = blockIdx.x;             // 0..511
    int t = threadIdx.x;              // 256 threads
    const float4* wr = (const float4*)(attn_W + (size_t)row * (2 * H));
    const float4* e  = (const float4*)(emb + (size_t)ids[0] * H);
    const float4* h  = (const float4*)hid;
    float acc = dot4(ld_stream(&wr[t]), e[t]) + dot4(ld_stream(&wr[256 + t]), h[t]);
    acc = blockReduceSum(acc);
    if (t == 0) g_a[row] = acc + attn_b[row];
    if (row == 0 && t == 0) g_maxbits = 0u;  // reset softmax-max for this run
}

// ---------------- K2: softmax(a) (redundant per block) + partial w@enc ------
// grid 64 = 4 h-blocks x 16 l-chunks, 256 threads
__global__ void k_attn_part(const float* __restrict__ enc, float* __restrict__ dout) {
    __shared__ float w[L];
    int t = threadIdx.x;
    float a0 = g_a[t], a1 = g_a[t + 256];
    float m = blockReduceMax(fmaxf(a0, a1));
    float e0 = expf(a0 - m), e1 = expf(a1 - m);
    w[t] = e0; w[t + 256] = e1;
    float s = blockReduceSum(e0 + e1);
    float inv = 1.0f / s;
    __syncthreads();

    int hb = blockIdx.x & 3, lc = blockIdx.x >> 2;
    int hcol = hb * 256 + t;
    const float* encp = enc + (size_t)(lc * 32) * H + hcol;
    const float* wp = &w[lc * 32];
    float acc = 0.0f;
#pragma unroll 8
    for (int l = 0; l < 32; l++) acc += wp[l] * __ldg(&encp[(size_t)l * H]);
    g_partial[lc][hcol] = acc * inv;

    if (blockIdx.x == 0) {  // emit attn_weights output
        dout[V + H + t]       = w[t] * inv;
        dout[V + H + 256 + t] = w[t + 256] * inv;
    }
}

// ---------------- K2b: reduce 16 partials -> attn_applied -------------------
__global__ void k_reduce_applied() {
    int hcol = blockIdx.x * 256 + threadIdx.x;  // grid 4 x 256
    float s = 0.0f;
#pragma unroll
    for (int c = 0; c < 16; c++) s += g_partial[c][hcol];
    g_applied[hcol] = s;
}

// ---------------- K3: x = relu(combine), gh = h0 @ W_hh.T + b_hh ------------
// grid 4096: blocks [0,1024) -> x rows, [1024,4096) -> gh rows
__global__ void k_xgh(const int* __restrict__ ids, const float* __restrict__ hid,
                      const float* __restrict__ emb,
                      const float* __restrict__ comb_W, const float* __restrict__ comb_b,
                      const float* __restrict__ W_hh, const float* __restrict__ b_hh) {
    int b = blockIdx.x, t = threadIdx.x;
    if (b < H) {
        const float4* wr = (const float4*)(comb_W + (size_t)b * (2 * H));
        const float4* e  = (const float4*)(emb + (size_t)ids[0] * H);
        const float4* ap = (const float4*)g_applied;
        float acc = dot4(ld_stream(&wr[t]), e[t]) + dot4(ld_stream(&wr[256 + t]), ap[t]);
        acc = blockReduceSum(acc);
        if (t == 0) g_x[b] = fmaxf(acc + comb_b[b], 0.0f);
    } else {
        int r = b - H;
        const float4* wr = (const float4*)(W_hh + (size_t)r * H);
        const float4* h  = (const float4*)hid;
        float acc = dot4(ld_stream(&wr[t]), h[t]);
        acc = blockReduceSum(acc);
        if (t == 0) g_gh[r] = acc + b_hh[r];
    }
}

// ---------------- K4: gi (3 dots per block) + GRU gates -> h_new ------------
// grid 1024 x 256
__global__ void k_gates(const float* __restrict__ hid, const float* __restrict__ W_ih,
                        const float* __restrict__ b_ih, float* __restrict__ dout) {
    int i = blockIdx.x, t = threadIdx.x;
    float4 xv = ((const float4*)g_x)[t];
    const float4* wr_r = (const float4*)(W_ih + (size_t)i * H);
    const float4* wr_z = (const float4*)(W_ih + (size_t)(i + H) * H);
    const float4* wr_n = (const float4*)(W_ih + (size_t)(i + 2 * H) * H);
    float ar = dot4(ld_stream(&wr_r[t]), xv);
    float az = dot4(ld_stream(&wr_z[t]), xv);
    float an = dot4(ld_stream(&wr_n[t]), xv);
    ar = blockReduceSum(ar);
    az = blockReduceSum(az);
    an = blockReduceSum(an);
    if (t == 0) {
        float r = sigm(ar + b_ih[i]         + g_gh[i]);
        float z = sigm(az + b_ih[i + H]     + g_gh[i + H]);
        float n = tanhf(an + b_ih[i + 2*H]  + r * g_gh[i + 2 * H]);
        float hnew = (1.0f - z) * n + z * hid[i];
        g_hnew[i] = hnew;
        dout[V + i] = hnew;     // h_new output slot
    }
}

// ---------------- K5: logits = h_new @ out_W.T + out_b (warp per row) -------
// grid ceil(V/8), 256 threads (8 warps)
__global__ void k_logits(const float* __restrict__ out_W, const float* __restrict__ out_b,
                         float* __restrict__ dout) {
    __shared__ float smax[8];
    int wid = threadIdx.x >> 5, lane = threadIdx.x & 31;
    int row = blockIdx.x * 8 + wid;
    float logit = -3.0e38f;
    if (row < V) {
        const float4* wr = (const float4*)(out_W + (size_t)row * H);
        const float4* h  = (const float4*)g_hnew;
        float acc = 0.0f;
#pragma unroll
        for (int it = 0; it < 8; it++) {
            acc += dot4(ld_stream(&wr[it * 32 + lane]), __ldg(&h[it * 32 + lane]));
        }
        acc = warpReduceSum(acc);
        if (lane == 0) {
            logit = acc + out_b[row];
            dout[row] = logit;
        }
    }
    if (lane == 0) smax[wid] = logit;
    __syncthreads();
    if (threadIdx.x == 0) {
        float m = smax[0];
#pragma unroll
        for (int k = 1; k < 8; k++) m = fmaxf(m, smax[k]);
        atomicMax(&g_maxbits, ordEnc(m));   // max is order-independent -> deterministic
    }
}

// ---------------- K6: deterministic partial sum-exp -------------------------
// grid 64 x 256
__global__ void k_sumexp(const float* __restrict__ dout) {
    float m = ordDec(g_maxbits);
    float acc = 0.0f;
    for (int i = blockIdx.x * 256 + threadIdx.x; i < V; i += 64 * 256)
        acc += expf(dout[i] - m);
    acc = blockReduceSum(acc);
    if (threadIdx.x == 0) g_sumpart[blockIdx.x] = acc;
}

// ---------------- K7: out[i] = logit[i] - (max + log(sumexp)) ---------------
// grid 128 x 256
__global__ void k_final(float* __restrict__ dout) {
    float s = 0.0f;
#pragma unroll
    for (int c = 0; c < 64; c++) s += g_sumpart[c];   // deterministic order
    float lz = ordDec(g_maxbits) + logf(s);
    for (int i = blockIdx.x * 256 + threadIdx.x; i < V; i += 128 * 256)
        dout[i] -= lz;
}

// ---------------- launcher --------------------------------------------------
extern "C" void kernel_launch(void* const* d_in, const int* in_sizes, int n_in,
                              void* d_out, int out_size) {
    const int*   ids     = (const int*)  d_in[0];
    const float* hidden  = (const float*)d_in[1];
    const float* enc     = (const float*)d_in[2];
    const float* emb     = (const float*)d_in[3];
    const float* attn_W  = (const float*)d_in[4];
    const float* attn_b  = (const float*)d_in[5];
    const float* comb_W  = (const float*)d_in[6];
    const float* comb_b  = (const float*)d_in[7];
    const float* W_ih    = (const float*)d_in[8];
    const float* W_hh    = (const float*)d_in[9];
    const float* b_ih    = (const float*)d_in[10];
    const float* b_hh    = (const float*)d_in[11];
    const float* out_W   = (const float*)d_in[12];
    const float* out_b   = (const float*)d_in[13];
    float* out = (float*)d_out;

    k_scores<<<L, 256>>>(ids, hidden, emb, attn_W, attn_b);
    k_attn_part<<<64, 256>>>(enc, out);
    k_reduce_applied<<<4, 256>>>();
    k_xgh<<<H + H3, 256>>>(ids, hidden, emb, comb_W, comb_b, W_hh, b_hh);
    k_gates<<<H, 256>>>(hidden, W_ih, b_ih, out);
    k_logits<<<(V + 7) / 8, 256>>>(out_W, out_b, out);
    k_sumexp<<<64, 256>>>(out);
    k_final<<<128, 256>>>(out);
}